// round 2
// baseline (speedup 1.0000x reference)
#include <cuda_runtime.h>
#include <cstdint>
#include <cstddef>

// Problem-shape constants (fixed by the dataset; asserted implicitly by sizes).
#define MAXN 100000
#define MAXE 1000000
#define NFEAT 64
#define NGRAPH 64

// ---------------- device scratch (no allocations allowed) ----------------
__device__ float g_A[(size_t)MAXN * NFEAT];   // current node features h
__device__ float g_B[(size_t)MAXN * NFEAT];   // hs = (h@W)*dinv
__device__ int   g_cnt[MAXN];                 // in-degree (without self loop)
__device__ int   g_excl[MAXN];                // block-local exclusive scan
__device__ int   g_off[MAXN + 1];             // CSR offsets
__device__ int   g_cur[MAXN];                 // placement cursors
__device__ int   g_srcs[MAXE];                // CSR column (src) indices
__device__ float g_dinv[MAXN];                // rsqrt(deg)
__device__ int   g_bsum[128];
__device__ int   g_bbase[128];
__device__ float g_sums[NGRAPH * NFEAT];      // pooled sums
__device__ int   g_gcnt[NGRAPH];              // nodes per graph

// ---------------- f32x2 packed FMA helpers (sm_100+) ----------------
__device__ __forceinline__ unsigned long long fma_f32x2(unsigned long long a,
                                                        unsigned long long b,
                                                        unsigned long long c) {
    unsigned long long d;
    asm("fma.rn.f32x2 %0, %1, %2, %3;" : "=l"(d) : "l"(a), "l"(b), "l"(c));
    return d;
}
__device__ __forceinline__ unsigned long long pack2(float x, float y) {
    unsigned long long d;
    asm("mov.b64 %0, {%1, %2};" : "=l"(d) : "f"(x), "f"(y));
    return d;
}

// ---------------- setup kernels ----------------
__global__ void k_zero(int N) {
    int i = blockIdx.x * blockDim.x + threadIdx.x;
    if (i < N) g_cnt[i] = 0;
    if (i < NGRAPH * NFEAT) g_sums[i] = 0.f;
    if (i < NGRAPH) g_gcnt[i] = 0;
}

__global__ void k_hist(const int* __restrict__ ei, int E) {
    int e = blockIdx.x * blockDim.x + threadIdx.x;
    if (e < E) atomicAdd(&g_cnt[ei[E + e]], 1);
}

__global__ void k_scan1(int N) {
    __shared__ int sm[1024];
    int t = threadIdx.x;
    int i = blockIdx.x * 1024 + t;
    int v = (i < N) ? g_cnt[i] : 0;
    sm[t] = v;
    __syncthreads();
    #pragma unroll
    for (int d = 1; d < 1024; d <<= 1) {
        int xv = (t >= d) ? sm[t - d] : 0;
        __syncthreads();
        sm[t] += xv;
        __syncthreads();
    }
    if (i < N) g_excl[i] = sm[t] - v;
    if (t == 1023) g_bsum[blockIdx.x] = sm[1023];
}

__global__ void k_scan2(int nb, int N) {
    __shared__ int sm[128];
    int t = threadIdx.x;
    int v = (t < nb) ? g_bsum[t] : 0;
    sm[t] = v;
    __syncthreads();
    #pragma unroll
    for (int d = 1; d < 128; d <<= 1) {
        int xv = (t >= d) ? sm[t - d] : 0;
        __syncthreads();
        sm[t] += xv;
        __syncthreads();
    }
    if (t < nb) g_bbase[t] = sm[t] - v;
    if (t == 127) g_off[N] = sm[127];
}

__global__ void k_scan3(int N) {
    int i = blockIdx.x * 1024 + threadIdx.x;
    if (i < N) {
        int o = g_excl[i] + g_bbase[blockIdx.x];
        g_off[i] = o;
        g_cur[i] = o;
        g_dinv[i] = rsqrtf((float)(g_cnt[i] + 1));  // +1 for self loop
    }
}

__global__ void k_place(const int* __restrict__ ei, int E) {
    int e = blockIdx.x * blockDim.x + threadIdx.x;
    if (e < E) {
        int s = ei[e];
        int d = ei[E + e];
        int p = atomicAdd(&g_cur[d], 1);
        g_srcs[p] = s;
    }
}

// ---------------- GEMM: hs = (X @ W) * dinv ----------------
// 64-row tile per block; 256 threads as 16x16 grid, 4 rows x 4 cols each.
// Row pairs packed for f32x2 for free out of smem float4; W broadcast-packed.
__global__ void __launch_bounds__(256) k_gemm(const float* __restrict__ Xext,
                                              const float* __restrict__ W,
                                              int N, int useExt) {
    __shared__ float xs[64][65];
    __shared__ __align__(16) float ws[64][64];
    const float* __restrict__ X = useExt ? Xext : g_A;
    int t = threadIdx.x;
    int base = blockIdx.x * 64;

    {
        const float4* w4 = (const float4*)W;
        float4* s4 = (float4*)&ws[0][0];
        #pragma unroll
        for (int q = 0; q < 4; q++) s4[q * 256 + t] = w4[q * 256 + t];
    }
    #pragma unroll
    for (int it = 0; it < 4; it++) {
        int q = it * 256 + t;
        int row = q >> 4;
        int kc = (q & 15) << 2;
        float4 v = make_float4(0.f, 0.f, 0.f, 0.f);
        if (base + row < N) v = *(const float4*)(X + (size_t)(base + row) * 64 + kc);
        xs[row][kc + 0] = v.x; xs[row][kc + 1] = v.y;
        xs[row][kc + 2] = v.z; xs[row][kc + 3] = v.w;
    }
    __syncthreads();

    int r = t >> 4;   // rows 4r..4r+3
    int c = t & 15;   // cols 4c..4c+3
    unsigned long long acc[4][2];
    #pragma unroll
    for (int j = 0; j < 4; j++) { acc[j][0] = 0ull; acc[j][1] = 0ull; }

    #pragma unroll 8
    for (int k = 0; k < 64; k++) {
        const ulonglong2 w2 = *(const ulonglong2*)&ws[k][c << 2];
        #pragma unroll
        for (int j = 0; j < 4; j++) {
            float xv = xs[(r << 2) + j][k];
            unsigned long long xd = pack2(xv, xv);
            acc[j][0] = fma_f32x2(xd, w2.x, acc[j][0]);
            acc[j][1] = fma_f32x2(xd, w2.y, acc[j][1]);
        }
    }
    #pragma unroll
    for (int j = 0; j < 4; j++) {
        int row = base + (r << 2) + j;
        if (row < N) {
            float dv = g_dinv[row];
            float2 a0 = *reinterpret_cast<float2*>(&acc[j][0]);
            float2 a1 = *reinterpret_cast<float2*>(&acc[j][1]);
            float4 o = make_float4(a0.x * dv, a0.y * dv, a1.x * dv, a1.y * dv);
            *(float4*)(g_B + (size_t)row * 64 + (c << 2)) = o;
        }
    }
}

// ---------------- aggregation: A[i] = dinv[i]*(B[i] + sum B[src]) + b ----------------
__global__ void __launch_bounds__(256) k_agg(const float* __restrict__ bias,
                                             int relu, int N) {
    int warp = (blockIdx.x * blockDim.x + threadIdx.x) >> 5;
    int lane = threadIdx.x & 31;
    if (warp >= N) return;
    const float2* __restrict__ B2 = (const float2*)g_B;
    float2 acc = B2[(size_t)warp * 32 + lane];  // self-loop term
    int beg = g_off[warp], end = g_off[warp + 1];
    int j = beg;
    for (; j + 4 <= end; j += 4) {
        int s0 = g_srcs[j + 0], s1 = g_srcs[j + 1];
        int s2 = g_srcs[j + 2], s3 = g_srcs[j + 3];
        float2 a0 = B2[(size_t)s0 * 32 + lane];
        float2 a1 = B2[(size_t)s1 * 32 + lane];
        float2 a2 = B2[(size_t)s2 * 32 + lane];
        float2 a3 = B2[(size_t)s3 * 32 + lane];
        acc.x += (a0.x + a1.x) + (a2.x + a3.x);
        acc.y += (a0.y + a1.y) + (a2.y + a3.y);
    }
    for (; j < end; j++) {
        int s = g_srcs[j];
        float2 a = B2[(size_t)s * 32 + lane];
        acc.x += a.x; acc.y += a.y;
    }
    float dv = g_dinv[warp];
    float2 b = ((const float2*)bias)[lane];
    float ox = fmaf(acc.x, dv, b.x);
    float oy = fmaf(acc.y, dv, b.y);
    if (relu) { ox = fmaxf(ox, 0.f); oy = fmaxf(oy, 0.f); }
    ((float2*)g_A)[(size_t)warp * 32 + lane] = make_float2(ox, oy);
}

// ---------------- mean pool (batch is sorted) ----------------
__global__ void __launch_bounds__(256) k_pool(const int* __restrict__ batch, int N) {
    int warp = (blockIdx.x * blockDim.x + threadIdx.x) >> 5;
    int lane = threadIdx.x & 31;
    int n0 = warp * 32;
    if (n0 >= N) return;
    int nend = min(n0 + 32, N);
    const float2* __restrict__ A2 = (const float2*)g_A;
    float2 acc = make_float2(0.f, 0.f);
    int cur = batch[n0];
    int cnt = 0;
    for (int n = n0; n < nend; n++) {
        int g = batch[n];
        if (g != cur) {
            atomicAdd(&g_sums[cur * 64 + 2 * lane], acc.x);
            atomicAdd(&g_sums[cur * 64 + 2 * lane + 1], acc.y);
            if (lane == 0) atomicAdd(&g_gcnt[cur], cnt);
            acc = make_float2(0.f, 0.f); cnt = 0; cur = g;
        }
        float2 v = A2[(size_t)n * 32 + lane];
        acc.x += v.x; acc.y += v.y; cnt++;
    }
    atomicAdd(&g_sums[cur * 64 + 2 * lane], acc.x);
    atomicAdd(&g_sums[cur * 64 + 2 * lane + 1], acc.y);
    if (lane == 0) atomicAdd(&g_gcnt[cur], cnt);
}

__global__ void k_final(const float* __restrict__ Wlin,
                        const float* __restrict__ blin,
                        float* __restrict__ out) {
    int t = threadIdx.x;
    if (t >= NGRAPH * 2) return;
    int g = t >> 1, o = t & 1;
    float cnt = fmaxf((float)g_gcnt[g], 1.f);
    float s = 0.f;
    #pragma unroll
    for (int f = 0; f < 64; f++) s += g_sums[g * 64 + f] * Wlin[f * 2 + o];
    out[g * 2 + o] = s / cnt + blin[o];
}

// ---------------- launch ----------------
extern "C" void kernel_launch(void* const* d_in, const int* in_sizes, int n_in,
                              void* d_out, int out_size) {
    const float* x     = (const float*)d_in[0];
    const int*   ei    = (const int*)d_in[1];
    const int*   batch = (const int*)d_in[2];
    const float* W1 = (const float*)d_in[3];
    const float* b1 = (const float*)d_in[4];
    const float* W2 = (const float*)d_in[5];
    const float* b2 = (const float*)d_in[6];
    const float* W3 = (const float*)d_in[7];
    const float* b3 = (const float*)d_in[8];
    const float* Wl = (const float*)d_in[9];
    const float* bl = (const float*)d_in[10];
    float* out = (float*)d_out;

    int N = in_sizes[0] / NFEAT;   // 100000
    int E = in_sizes[1] / 2;       // 1000000
    int nb = (N + 1023) / 1024;    // 98 (must be <= 128)

    // CSR build (reused by all 3 layers)
    k_zero<<<(N + 255) / 256, 256>>>(N);
    k_hist<<<(E + 255) / 256, 256>>>(ei, E);
    k_scan1<<<nb, 1024>>>(N);
    k_scan2<<<1, 128>>>(nb, N);
    k_scan3<<<nb, 1024>>>(N);
    k_place<<<(E + 255) / 256, 256>>>(ei, E);

    int gemmBlocks = (N + 63) / 64;
    int aggBlocks  = (N + 7) / 8;

    k_gemm<<<gemmBlocks, 256>>>(x, W1, N, 1);
    k_agg<<<aggBlocks, 256>>>(b1, 1, N);
    k_gemm<<<gemmBlocks, 256>>>(nullptr, W2, N, 0);
    k_agg<<<aggBlocks, 256>>>(b2, 1, N);
    k_gemm<<<gemmBlocks, 256>>>(nullptr, W3, N, 0);
    k_agg<<<aggBlocks, 256>>>(b3, 0, N);

    int poolWarps = (N + 31) / 32;
    k_pool<<<(poolWarps + 7) / 8, 256>>>(batch, N);
    k_final<<<1, 128>>>(Wl, bl, out);
}